// round 5
// baseline (speedup 1.0000x reference)
#include <cuda_runtime.h>
#include <math.h>
#include <stdint.h>

// ---------------------------------------------------------------------------
// Problem constants
// ---------------------------------------------------------------------------
#define BATCH   32
#define L_SER   32768
#define PATCH   32          // PS
#define DMODEL  256         // D
#define T_TOK   1024        // L / PS
#define QKV_N   768         // 3*D
#define ROWS    (BATCH * T_TOK)   // 32768 token rows

typedef unsigned long long u64;

// ---------------------------------------------------------------------------
// Device scratch (static: no allocation allowed)
// ---------------------------------------------------------------------------
__device__ float  g_patches[BATCH * L_SER];                 // x_norm == patches, 4 MB
__device__ float  g_qkv[(size_t)ROWS * QKV_N];              // 96 MB
__device__ float  g_attnout[(size_t)ROWS * DMODEL];         // 32 MB
__device__ float  g_Weff[PATCH * QKV_N];                    // W_proj @ W_qkv
__device__ float  g_beff[QKV_N];
__device__ float  g_Wph[DMODEL * PATCH];                    // W_out @ W_head
__device__ float  g_bph[PATCH];
__device__ double g_loss_acc;

// ---------------------------------------------------------------------------
// Packed f32x2 helpers (Blackwell FFMA2 path)
// ---------------------------------------------------------------------------
__device__ __forceinline__ void ffma2(u64 &d, u64 a, u64 b) {
    asm("fma.rn.f32x2 %0, %1, %2, %0;" : "+l"(d) : "l"(a), "l"(b));
}
__device__ __forceinline__ u64 fmul2(u64 a, u64 b) {
    u64 d; asm("mul.rn.f32x2 %0, %1, %2;" : "=l"(d) : "l"(a), "l"(b)); return d;
}
__device__ __forceinline__ u64 pack2(float x) {
    u64 d; unsigned u = __float_as_uint(x);
    asm("mov.b64 %0, {%1, %1};" : "=l"(d) : "r"(u)); return d;
}
__device__ __forceinline__ float f2lo(u64 v) { return __uint_as_float((unsigned)v); }
__device__ __forceinline__ float f2hi(u64 v) { return __uint_as_float((unsigned)(v >> 32)); }

// cp.async (LDGSTS) helpers
__device__ __forceinline__ void cp_async16(uint32_t saddr, const void* gptr) {
    asm volatile("cp.async.cg.shared.global [%0], [%1], 16;"
                 :: "r"(saddr), "l"(__cvta_generic_to_global(gptr)) : "memory");
}
#define CP_COMMIT() asm volatile("cp.async.commit_group;" ::: "memory")
#define CP_WAIT(n)  asm volatile("cp.async.wait_group %0;" :: "n"(n) : "memory")

// ---------------------------------------------------------------------------
// K1: fold weights + zero loss accumulator
// ---------------------------------------------------------------------------
__global__ void prep_kernel(const float* __restrict__ Wproj, const float* __restrict__ bproj,
                            const float* __restrict__ Wqkv,  const float* __restrict__ bqkv,
                            const float* __restrict__ Wout,  const float* __restrict__ bout,
                            const float* __restrict__ Whead, const float* __restrict__ bhead)
{
    int idx = blockIdx.x * blockDim.x + threadIdx.x;
    if (idx == 0) g_loss_acc = 0.0;

    if (idx < PATCH * QKV_N) {
        int k = idx / QKV_N, j = idx % QKV_N;
        float acc = 0.f;
        #pragma unroll 8
        for (int d = 0; d < DMODEL; d++)
            acc = fmaf(Wproj[k * DMODEL + d], Wqkv[d * QKV_N + j], acc);
        g_Weff[idx] = acc;
    } else if (idx < PATCH * QKV_N + QKV_N) {
        int j = idx - PATCH * QKV_N;
        float acc = bqkv[j];
        #pragma unroll 8
        for (int d = 0; d < DMODEL; d++)
            acc = fmaf(bproj[d], Wqkv[d * QKV_N + j], acc);
        g_beff[j] = acc;
    } else if (idx < PATCH * QKV_N + QKV_N + DMODEL * PATCH) {
        int t = idx - (PATCH * QKV_N + QKV_N);
        int d = t / PATCH, p = t % PATCH;
        float acc = 0.f;
        #pragma unroll 8
        for (int e = 0; e < DMODEL; e++)
            acc = fmaf(Wout[d * DMODEL + e], Whead[e * PATCH + p], acc);
        g_Wph[t] = acc;
    } else if (idx < PATCH * QKV_N + QKV_N + DMODEL * PATCH + PATCH) {
        int p = idx - (PATCH * QKV_N + QKV_N + DMODEL * PATCH);
        float acc = bhead[p];
        #pragma unroll 8
        for (int e = 0; e < DMODEL; e++)
            acc = fmaf(bout[e], Whead[e * PATCH + p], acc);
        g_bph[p] = acc;
    }
}

// ---------------------------------------------------------------------------
// K2: instance norm over full series per batch row (ddof=1, +1e-5 on std)
// ---------------------------------------------------------------------------
__global__ void instnorm_kernel(const float* __restrict__ x)
{
    int b   = blockIdx.x;
    int tid = threadIdx.x;
    const float* xr = x + (size_t)b * L_SER;
    float*       pr = g_patches + (size_t)b * L_SER;

    float s = 0.f, ss = 0.f;
    for (int i = tid * 4; i < L_SER; i += 256 * 4) {
        float4 v = *(const float4*)(xr + i);
        s  += v.x + v.y + v.z + v.w;
        ss += v.x * v.x + v.y * v.y + v.z * v.z + v.w * v.w;
    }
    #pragma unroll
    for (int w = 16; w >= 1; w >>= 1) {
        s  += __shfl_xor_sync(0xffffffffu, s,  w);
        ss += __shfl_xor_sync(0xffffffffu, ss, w);
    }
    __shared__ float rs[8], rss[8];
    __shared__ float sh_mean, sh_inv;
    int lane = tid & 31, warp = tid >> 5;
    if (lane == 0) { rs[warp] = s; rss[warp] = ss; }
    __syncthreads();
    if (tid == 0) {
        float ts = 0.f, tss = 0.f;
        #pragma unroll
        for (int w = 0; w < 8; w++) { ts += rs[w]; tss += rss[w]; }
        float mean = ts / (float)L_SER;
        float var  = (tss - (float)L_SER * mean * mean) / (float)(L_SER - 1);
        float std  = sqrtf(var) + 1e-5f;
        sh_mean = mean;
        sh_inv  = 1.0f / std;
    }
    __syncthreads();
    float mean = sh_mean, inv = sh_inv;
    for (int i = tid * 4; i < L_SER; i += 256 * 4) {
        float4 v = *(const float4*)(xr + i);
        v.x = (v.x - mean) * inv; v.y = (v.y - mean) * inv;
        v.z = (v.z - mean) * inv; v.w = (v.w - mean) * inv;
        *(float4*)(pr + i) = v;
    }
}

// ---------------------------------------------------------------------------
// K3: qkv = patches[32768,32] @ Weff[32,768] + beff  (f32x2 packed FMA)
// ---------------------------------------------------------------------------
__global__ __launch_bounds__(256) void qkv_gemm_kernel()
{
    __shared__ __align__(16) float Ap[64][33];
    __shared__ __align__(16) float Bp[32][68];

    int tid = threadIdx.x;
    int ty  = tid >> 4, tx = tid & 15;
    int ty4 = ty * 4, tx4 = tx * 4;
    int row0 = blockIdx.y * 64;
    int col0 = blockIdx.x * 64;

    for (int i = tid; i < 64 * 32; i += 256) {
        int r = i >> 5, k = i & 31;
        Ap[r][k] = g_patches[(size_t)(row0 + r) * PATCH + k];
    }
    for (int i = tid; i < 32 * 64; i += 256) {
        int k = i >> 6, c = i & 63;
        Bp[k][c] = g_Weff[k * QKV_N + col0 + c];
    }
    __syncthreads();

    u64 acc2[4][2];
    #pragma unroll
    for (int i = 0; i < 4; i++) { acc2[i][0] = 0ull; acc2[i][1] = 0ull; }

    #pragma unroll
    for (int k = 0; k < 32; k++) {
        u64 pa[4];
        #pragma unroll
        for (int i = 0; i < 4; i++) pa[i] = pack2(Ap[ty4 + i][k]);
        ulonglong2 b2 = *(const ulonglong2*)&Bp[k][tx4];
        #pragma unroll
        for (int i = 0; i < 4; i++) {
            ffma2(acc2[i][0], pa[i], b2.x);
            ffma2(acc2[i][1], pa[i], b2.y);
        }
    }

    float4 bias = *(const float4*)&g_beff[col0 + tx4];
    #pragma unroll
    for (int i = 0; i < 4; i++) {
        float4 o;
        o.x = f2lo(acc2[i][0]) + bias.x;
        o.y = f2hi(acc2[i][0]) + bias.y;
        o.z = f2lo(acc2[i][1]) + bias.z;
        o.w = f2hi(acc2[i][1]) + bias.w;
        *(float4*)(g_qkv + (size_t)(row0 + ty4 + i) * QKV_N + col0 + tx4) = o;
    }
}

// ---------------------------------------------------------------------------
// K4: causal flash attention, fp32 via packed f32x2 FMA.
//   Grid 512 (heavy blocks first). BM=BN=64, D=256.
//   - Column mapping tx + 16*jj in the S phase -> conflict-free Ks reads.
//   - P stored duplicated ({p,p} u64) -> packed P@V operands, no per-step packs.
//   - cp.async double-buffered K/V chunks (8 x 16KB phases per j-iter).
// ---------------------------------------------------------------------------
#define KV_STRIDE 68     // floats per row
#define QS_STRIDE 260    // floats per row (pad so 4-row delta hits disjoint banks)
#define PS_STRIDE 66     // u64 per row
#define ATTN_SMEM (64*QS_STRIDE*4 + 2*64*KV_STRIDE*4 + 64*PS_STRIDE*8)  // 135168 B

__global__ __launch_bounds__(256, 1) void attention_kernel()
{
    extern __shared__ __align__(16) float smem[];
    float* Qs  = smem;                                  // [64][QS_STRIDE]
    float* KV  = Qs + 64 * QS_STRIDE;                   // [2][64][KV_STRIDE]
    u64*   Ps2 = (u64*)(KV + 2 * 64 * KV_STRIDE);       // [64][PS_STRIDE]

    int tid = threadIdx.x;
    int ty  = tid >> 4, tx = tid & 15;
    int ty4 = ty * 4,  tx4 = tx * 4;
    int id  = blockIdx.x;
    int qb  = 15 - (id >> 5);       // heavy q-blocks launch first
    int b   = id & 31;

    uint32_t kv_s0 = (uint32_t)__cvta_generic_to_shared(KV);

    // prefetch phase (j=0, p=0): K chunk dc=0 into buffer 0
    {
        const float* nb = g_qkv + ((size_t)b * T_TOK) * QKV_N + DMODEL;
        #pragma unroll
        for (int t = 0; t < 4; t++) {
            int idx = tid + t * 256;
            int r = idx >> 4, c4 = idx & 15;
            cp_async16(kv_s0 + (uint32_t)(r * KV_STRIDE + c4 * 4) * 4,
                       nb + (size_t)r * QKV_N + c4 * 4);
        }
        CP_COMMIT();
    }

    // load Q block: 64 rows x 256 cols
    const float* qbase = g_qkv + ((size_t)b * T_TOK + qb * 64) * QKV_N;
    #pragma unroll
    for (int t = 0; t < 16; t++) {
        int idx = tid + t * 256;
        int r = idx >> 6, c4 = idx & 63;
        *(float4*)&Qs[r * QS_STRIDE + c4 * 4] = *(const float4*)(qbase + (size_t)r * QKV_N + c4 * 4);
    }

    float m[4], l[4];
    u64 O2[4][8];
    #pragma unroll
    for (int i = 0; i < 4; i++) {
        m[i] = -1e30f; l[i] = 0.f;
        #pragma unroll
        for (int k = 0; k < 8; k++) O2[i][k] = 0ull;
    }

    int cur = 0;
    for (int j = 0; j <= qb; j++) {
        u64 S2[4][4];
        #pragma unroll
        for (int i = 0; i < 4; i++)
            #pragma unroll
            for (int jj = 0; jj < 4; jj++) S2[i][jj] = 0ull;

        for (int p = 0; p < 8; p++) {
            __syncthreads();                      // everyone done with buf[cur^1]
            int np = p + 1, nj = j;
            if (np == 8) { np = 0; nj = j + 1; }
            if (nj <= qb) {
                const float* nb = g_qkv + ((size_t)b * T_TOK + nj * 64) * QKV_N
                                + DMODEL + ((np >= 4) ? DMODEL : 0) + (np & 3) * 64;
                uint32_t dstb = kv_s0 + (uint32_t)((cur ^ 1) * 64 * KV_STRIDE) * 4;
                #pragma unroll
                for (int t = 0; t < 4; t++) {
                    int idx = tid + t * 256;
                    int r = idx >> 4, c4 = idx & 15;
                    cp_async16(dstb + (uint32_t)(r * KV_STRIDE + c4 * 4) * 4,
                               nb + (size_t)r * QKV_N + c4 * 4);
                }
                CP_COMMIT();
                CP_WAIT(1);                       // current phase's data arrived
            } else {
                CP_WAIT(0);
            }
            __syncthreads();                      // arrival visible to all

            const float* buf = KV + cur * 64 * KV_STRIDE;

            if (p < 4) {
                // ---- S chunk: dc = p ----
                int dc = p;
                #pragma unroll
                for (int d = 0; d < 64; d += 4) {
                    ulonglong2 qv[4], kv[4];
                    #pragma unroll
                    for (int i = 0; i < 4; i++)
                        qv[i] = *(const ulonglong2*)&Qs[(ty4 + i) * QS_STRIDE + dc * 64 + d];
                    #pragma unroll
                    for (int jj = 0; jj < 4; jj++)
                        kv[jj] = *(const ulonglong2*)&buf[(tx + 16 * jj) * KV_STRIDE + d];
                    #pragma unroll
                    for (int i = 0; i < 4; i++)
                        #pragma unroll
                        for (int jj = 0; jj < 4; jj++) {
                            ffma2(S2[i][jj], qv[i].x, kv[jj].x);
                            ffma2(S2[i][jj], qv[i].y, kv[jj].y);
                        }
                }

                if (p == 3) {
                    // ---- scale, mask, online softmax, write duplicated P ----
                    bool diag = (j == qb);
                    #pragma unroll
                    for (int i = 0; i < 4; i++) {
                        int row = ty4 + i;
                        float sv[4];
                        float mx = -1e30f;
                        #pragma unroll
                        for (int jj = 0; jj < 4; jj++) {
                            float s = (f2lo(S2[i][jj]) + f2hi(S2[i][jj])) * 0.0625f;
                            int col = tx + 16 * jj;
                            if (diag && col > row) s = -1e30f;
                            sv[jj] = s;
                            mx = fmaxf(mx, s);
                        }
                        #pragma unroll
                        for (int w = 8; w >= 1; w >>= 1)
                            mx = fmaxf(mx, __shfl_xor_sync(0xffffffffu, mx, w));
                        float mnew  = fmaxf(m[i], mx);
                        float alpha = __expf(m[i] - mnew);
                        float ls = 0.f;
                        #pragma unroll
                        for (int jj = 0; jj < 4; jj++) {
                            float pe = __expf(sv[jj] - mnew);
                            Ps2[row * PS_STRIDE + tx + 16 * jj] = pack2(pe);
                            ls += pe;
                        }
                        #pragma unroll
                        for (int w = 8; w >= 1; w >>= 1)
                            ls += __shfl_xor_sync(0xffffffffu, ls, w);
                        l[i] = l[i] * alpha + ls;
                        m[i] = mnew;
                        u64 a2 = pack2(alpha);
                        #pragma unroll
                        for (int k = 0; k < 8; k++) O2[i][k] = fmul2(O2[i][k], a2);
                    }
                }
            } else {
                // ---- O chunk: dc = p - 4 ----
                int dc = p - 4;
                #pragma unroll
                for (int s = 0; s < 64; s += 4) {
                    ulonglong2 pva[4], pvb[4];
                    #pragma unroll
                    for (int i = 0; i < 4; i++) {
                        pva[i] = *(const ulonglong2*)&Ps2[(ty4 + i) * PS_STRIDE + s];
                        pvb[i] = *(const ulonglong2*)&Ps2[(ty4 + i) * PS_STRIDE + s + 2];
                    }
                    #pragma unroll
                    for (int ss = 0; ss < 4; ss++) {
                        ulonglong2 vv = *(const ulonglong2*)&buf[(s + ss) * KV_STRIDE + tx4];
                        #pragma unroll
                        for (int i = 0; i < 4; i++) {
                            u64 pp = (ss == 0) ? pva[i].x : (ss == 1) ? pva[i].y
                                   : (ss == 2) ? pvb[i].x : pvb[i].y;
                            ffma2(O2[i][dc * 2 + 0], pp, vv.x);
                            ffma2(O2[i][dc * 2 + 1], pp, vv.y);
                        }
                    }
                }
            }
            cur ^= 1;
        }
    }

    // ---- normalize + store ----
    float* obase = g_attnout + ((size_t)b * T_TOK + qb * 64) * DMODEL;
    #pragma unroll
    for (int i = 0; i < 4; i++) {
        float inv = 1.0f / l[i];
        #pragma unroll
        for (int dc = 0; dc < 4; dc++) {
            float4 o;
            o.x = f2lo(O2[i][dc * 2 + 0]) * inv;
            o.y = f2hi(O2[i][dc * 2 + 0]) * inv;
            o.z = f2lo(O2[i][dc * 2 + 1]) * inv;
            o.w = f2hi(O2[i][dc * 2 + 1]) * inv;
            *(float4*)(obase + (size_t)(ty4 + i) * DMODEL + dc * 64 + tx4) = o;
        }
    }
}

// ---------------------------------------------------------------------------
// K5: pred = attnout @ Wph + bph, fused next-patch MSE accumulation.
// ---------------------------------------------------------------------------
__global__ __launch_bounds__(256) void pred_loss_kernel()
{
    __shared__ float Ws[DMODEL * PATCH];
    int tid = threadIdx.x;
    for (int i = tid; i < DMODEL * PATCH; i += 256) Ws[i] = g_Wph[i];
    __syncthreads();

    int lane = tid & 31, warp = tid >> 5;
    int gw = blockIdx.x * 8 + warp;
    int nw = gridDim.x * 8;
    float bias = g_bph[lane];

    float lsum = 0.f;
    for (int row = gw; row < ROWS; row += nw) {
        const float* orow = g_attnout + (size_t)row * DMODEL;
        float acc = bias;
        #pragma unroll
        for (int kb = 0; kb < 8; kb++) {
            float ov = orow[kb * 32 + lane];
            #pragma unroll
            for (int k2 = 0; k2 < 32; k2++) {
                float o = __shfl_sync(0xffffffffu, ov, k2);
                acc = fmaf(o, Ws[(kb * 32 + k2) * 32 + lane], acc);
            }
        }
        if ((row & (T_TOK - 1)) != T_TOK - 1) {
            float d = acc - g_patches[(size_t)(row + 1) * PATCH + lane];
            lsum = fmaf(d, d, lsum);
        }
    }
    #pragma unroll
    for (int w = 16; w >= 1; w >>= 1)
        lsum += __shfl_xor_sync(0xffffffffu, lsum, w);
    if (lane == 0) atomicAdd(&g_loss_acc, (double)lsum);
}

// ---------------------------------------------------------------------------
// K6: finalize
// ---------------------------------------------------------------------------
__global__ void finalize_kernel(float* out)
{
    out[0] = (float)(g_loss_acc / (double)(BATCH * (T_TOK - 1) * PATCH));
}

// ---------------------------------------------------------------------------
// Launch
// ---------------------------------------------------------------------------
extern "C" void kernel_launch(void* const* d_in, const int* in_sizes, int n_in,
                              void* d_out, int out_size)
{
    const float* x      = (const float*)d_in[0];
    const float* Wproj  = (const float*)d_in[1];
    const float* bproj  = (const float*)d_in[2];
    const float* Wqkv   = (const float*)d_in[3];
    const float* bqkv   = (const float*)d_in[4];
    const float* Wout   = (const float*)d_in[5];
    const float* bout   = (const float*)d_in[6];
    const float* Whead  = (const float*)d_in[7];
    const float* bhead  = (const float*)d_in[8];
    float* out = (float*)d_out;

    cudaFuncSetAttribute(attention_kernel,
                         cudaFuncAttributeMaxDynamicSharedMemorySize, ATTN_SMEM);

    prep_kernel<<<132, 256>>>(Wproj, bproj, Wqkv, bqkv, Wout, bout, Whead, bhead);
    instnorm_kernel<<<BATCH, 256>>>(x);
    qkv_gemm_kernel<<<dim3(QKV_N / 64, ROWS / 64), 256>>>();
    attention_kernel<<<512, 256, ATTN_SMEM>>>();
    pred_loss_kernel<<<256, 256>>>();
    finalize_kernel<<<1, 1>>>(out);
}

// round 6
// speedup vs baseline: 3.7077x; 3.7077x over previous
#include <cuda_runtime.h>
#include <math.h>
#include <stdint.h>

// ---------------------------------------------------------------------------
// Problem constants
// ---------------------------------------------------------------------------
#define BATCH   32
#define L_SER   32768
#define PATCH   32          // PS
#define DMODEL  256         // D
#define T_TOK   1024        // L / PS
#define QKV_N   768         // 3*D
#define ROWS    (BATCH * T_TOK)   // 32768 token rows

// ---------------------------------------------------------------------------
// Device scratch (static: no allocation allowed)
// ---------------------------------------------------------------------------
__device__ float  g_patches[BATCH * L_SER];                 // x_norm == patches, 4 MB
__device__ float  g_qkv[(size_t)ROWS * QKV_N];              // 96 MB
__device__ float  g_attnout[(size_t)ROWS * DMODEL];         // 32 MB
__device__ float  g_Weff[PATCH * QKV_N];                    // W_proj @ W_qkv
__device__ float  g_beff[QKV_N];
__device__ float  g_Wph[DMODEL * PATCH];                    // W_out @ W_head
__device__ float  g_bph[PATCH];
__device__ double g_loss_acc;

// ---------------------------------------------------------------------------
// K1: fold weights + zero loss accumulator
// ---------------------------------------------------------------------------
__global__ void prep_kernel(const float* __restrict__ Wproj, const float* __restrict__ bproj,
                            const float* __restrict__ Wqkv,  const float* __restrict__ bqkv,
                            const float* __restrict__ Wout,  const float* __restrict__ bout,
                            const float* __restrict__ Whead, const float* __restrict__ bhead)
{
    int idx = blockIdx.x * blockDim.x + threadIdx.x;
    if (idx == 0) g_loss_acc = 0.0;

    if (idx < PATCH * QKV_N) {
        int k = idx / QKV_N, j = idx % QKV_N;
        float acc = 0.f;
        #pragma unroll 8
        for (int d = 0; d < DMODEL; d++)
            acc = fmaf(Wproj[k * DMODEL + d], Wqkv[d * QKV_N + j], acc);
        g_Weff[idx] = acc;
    } else if (idx < PATCH * QKV_N + QKV_N) {
        int j = idx - PATCH * QKV_N;
        float acc = bqkv[j];
        #pragma unroll 8
        for (int d = 0; d < DMODEL; d++)
            acc = fmaf(bproj[d], Wqkv[d * QKV_N + j], acc);
        g_beff[j] = acc;
    } else if (idx < PATCH * QKV_N + QKV_N + DMODEL * PATCH) {
        int t = idx - (PATCH * QKV_N + QKV_N);
        int d = t / PATCH, p = t % PATCH;
        float acc = 0.f;
        #pragma unroll 8
        for (int e = 0; e < DMODEL; e++)
            acc = fmaf(Wout[d * DMODEL + e], Whead[e * PATCH + p], acc);
        g_Wph[t] = acc;
    } else if (idx < PATCH * QKV_N + QKV_N + DMODEL * PATCH + PATCH) {
        int p = idx - (PATCH * QKV_N + QKV_N + DMODEL * PATCH);
        float acc = bhead[p];
        #pragma unroll 8
        for (int e = 0; e < DMODEL; e++)
            acc = fmaf(bout[e], Whead[e * PATCH + p], acc);
        g_bph[p] = acc;
    }
}

// ---------------------------------------------------------------------------
// K2: instance norm over full series per batch row (ddof=1, +1e-5 on std)
// ---------------------------------------------------------------------------
__global__ void instnorm_kernel(const float* __restrict__ x)
{
    int b   = blockIdx.x;
    int tid = threadIdx.x;
    const float* xr = x + (size_t)b * L_SER;
    float*       pr = g_patches + (size_t)b * L_SER;

    float s = 0.f, ss = 0.f;
    for (int i = tid * 4; i < L_SER; i += 256 * 4) {
        float4 v = *(const float4*)(xr + i);
        s  += v.x + v.y + v.z + v.w;
        ss += v.x * v.x + v.y * v.y + v.z * v.z + v.w * v.w;
    }
    #pragma unroll
    for (int w = 16; w >= 1; w >>= 1) {
        s  += __shfl_xor_sync(0xffffffffu, s,  w);
        ss += __shfl_xor_sync(0xffffffffu, ss, w);
    }
    __shared__ float rs[8], rss[8];
    __shared__ float sh_mean, sh_inv;
    int lane = tid & 31, warp = tid >> 5;
    if (lane == 0) { rs[warp] = s; rss[warp] = ss; }
    __syncthreads();
    if (tid == 0) {
        float ts = 0.f, tss = 0.f;
        #pragma unroll
        for (int w = 0; w < 8; w++) { ts += rs[w]; tss += rss[w]; }
        float mean = ts / (float)L_SER;
        float var  = (tss - (float)L_SER * mean * mean) / (float)(L_SER - 1);
        float std  = sqrtf(var) + 1e-5f;
        sh_mean = mean;
        sh_inv  = 1.0f / std;
    }
    __syncthreads();
    float mean = sh_mean, inv = sh_inv;
    for (int i = tid * 4; i < L_SER; i += 256 * 4) {
        float4 v = *(const float4*)(xr + i);
        v.x = (v.x - mean) * inv; v.y = (v.y - mean) * inv;
        v.z = (v.z - mean) * inv; v.w = (v.w - mean) * inv;
        *(float4*)(pr + i) = v;
    }
}

// ---------------------------------------------------------------------------
// K3: qkv = patches[32768,32] @ Weff[32,768] + beff  (scalar, R4 version)
// ---------------------------------------------------------------------------
__global__ __launch_bounds__(256) void qkv_gemm_kernel()
{
    __shared__ __align__(16) float Ap[64][33];
    __shared__ __align__(16) float Bp[32][68];

    int tid = threadIdx.x;
    int ty  = tid >> 4, tx = tid & 15;
    int row0 = blockIdx.y * 64;
    int col0 = blockIdx.x * 64;

    for (int i = tid; i < 64 * 32; i += 256) {
        int r = i >> 5, k = i & 31;
        Ap[r][k] = g_patches[(size_t)(row0 + r) * PATCH + k];
    }
    for (int i = tid; i < 32 * 64; i += 256) {
        int k = i >> 6, c = i & 63;
        Bp[k][c] = g_Weff[k * QKV_N + col0 + c];
    }
    __syncthreads();

    float acc[4][4];
    #pragma unroll
    for (int i = 0; i < 4; i++)
        #pragma unroll
        for (int j = 0; j < 4; j++) acc[i][j] = 0.f;

    #pragma unroll
    for (int k = 0; k < 32; k++) {
        float a[4];
        #pragma unroll
        for (int i = 0; i < 4; i++) a[i] = Ap[ty * 4 + i][k];
        float4 b4 = *(const float4*)&Bp[k][tx * 4];
        #pragma unroll
        for (int i = 0; i < 4; i++) {
            acc[i][0] = fmaf(a[i], b4.x, acc[i][0]);
            acc[i][1] = fmaf(a[i], b4.y, acc[i][1]);
            acc[i][2] = fmaf(a[i], b4.z, acc[i][2]);
            acc[i][3] = fmaf(a[i], b4.w, acc[i][3]);
        }
    }

    float4 bias = *(const float4*)&g_beff[col0 + tx * 4];
    #pragma unroll
    for (int i = 0; i < 4; i++) {
        float4 o;
        o.x = acc[i][0] + bias.x; o.y = acc[i][1] + bias.y;
        o.z = acc[i][2] + bias.z; o.w = acc[i][3] + bias.w;
        *(float4*)(g_qkv + (size_t)(row0 + ty * 4 + i) * QKV_N + col0 + tx * 4) = o;
    }
}

// ---------------------------------------------------------------------------
// K4: causal flash attention, scalar fp32.
//   BM=BN=64, D=256. Q, K, V ALL fully resident in SMEM per j-iter
//   (217 KB total) -> only 2 __syncthreads + 1 __syncwarp per j-iter.
//   S-phase column mapping col = tx + 16*jj -> conflict-free Ks reads
//   (lane stride 260 floats = 4 banks apart, each 8-lane LDS.128 phase
//   tiles all 32 banks).
//   P rows are written and read by the same half-warp -> __syncwarp only.
// ---------------------------------------------------------------------------
#define SMS  260    // Q/K/V row stride in floats
#define PSS  68     // P row stride in floats
#define ATTN_SMEM ((3 * 64 * SMS + 64 * PSS) * 4)   // 217088 bytes

__global__ __launch_bounds__(256, 1) void attention_kernel()
{
    extern __shared__ __align__(16) float smem[];
    float* Qs = smem;                   // [64][260]
    float* Ks = Qs + 64 * SMS;          // [64][260]
    float* Vs = Ks + 64 * SMS;          // [64][260]
    float* Ps = Vs + 64 * SMS;          // [64][68]

    int tid = threadIdx.x;
    int ty  = tid >> 4, tx = tid & 15;
    int ty4 = ty * 4,  tx4 = tx * 4;
    int id  = blockIdx.x;
    int qb  = 15 - (id >> 5);           // heavy q-blocks launch first
    int b   = id & 31;

    // load Q block: 64 rows x 256 cols
    const float* qbase = g_qkv + ((size_t)b * T_TOK + qb * 64) * QKV_N;
    #pragma unroll
    for (int t = 0; t < 16; t++) {
        int idx = tid + t * 256;
        int r = idx >> 6, c4 = idx & 63;
        *(float4*)&Qs[r * SMS + c4 * 4] = *(const float4*)(qbase + (size_t)r * QKV_N + c4 * 4);
    }

    float m[4], l[4];
    float4 O[4][4];
    #pragma unroll
    for (int i = 0; i < 4; i++) {
        m[i] = -1e30f; l[i] = 0.f;
        #pragma unroll
        for (int dc = 0; dc < 4; dc++) O[i][dc] = make_float4(0.f, 0.f, 0.f, 0.f);
    }

    for (int j = 0; j <= qb; j++) {
        const float* kb = g_qkv + ((size_t)b * T_TOK + j * 64) * QKV_N + DMODEL;
        const float* vb = kb + DMODEL;

        __syncthreads();   // previous iter done reading K/V (and Q load visible, j=0)
        #pragma unroll
        for (int t = 0; t < 16; t++) {
            int idx = tid + t * 256;
            int r = idx >> 6, c4 = idx & 63;
            *(float4*)&Ks[r * SMS + c4 * 4] = *(const float4*)(kb + (size_t)r * QKV_N + c4 * 4);
        }
        #pragma unroll
        for (int t = 0; t < 16; t++) {
            int idx = tid + t * 256;
            int r = idx >> 6, c4 = idx & 63;
            *(float4*)&Vs[r * SMS + c4 * 4] = *(const float4*)(vb + (size_t)r * QKV_N + c4 * 4);
        }
        __syncthreads();   // K/V visible

        // ---- S = Q @ K^T, full 256 depth. col(jj) = tx + 16*jj ----
        float S[4][4];
        #pragma unroll
        for (int i = 0; i < 4; i++)
            #pragma unroll
            for (int jj = 0; jj < 4; jj++) S[i][jj] = 0.f;

        #pragma unroll 4
        for (int d = 0; d < 256; d += 4) {
            float4 qv[4], kv[4];
            #pragma unroll
            for (int i = 0; i < 4; i++)  qv[i]  = *(const float4*)&Qs[(ty4 + i) * SMS + d];
            #pragma unroll
            for (int jj = 0; jj < 4; jj++) kv[jj] = *(const float4*)&Ks[(tx + 16 * jj) * SMS + d];
            #pragma unroll
            for (int i = 0; i < 4; i++)
                #pragma unroll
                for (int jj = 0; jj < 4; jj++) {
                    S[i][jj] = fmaf(qv[i].x, kv[jj].x, S[i][jj]);
                    S[i][jj] = fmaf(qv[i].y, kv[jj].y, S[i][jj]);
                    S[i][jj] = fmaf(qv[i].z, kv[jj].z, S[i][jj]);
                    S[i][jj] = fmaf(qv[i].w, kv[jj].w, S[i][jj]);
                }
        }

        // ---- scale, causal mask, online softmax, write P (scalar) ----
        bool diag = (j == qb);
        #pragma unroll
        for (int i = 0; i < 4; i++) {
            int row = ty4 + i;
            float mx = -1e30f;
            #pragma unroll
            for (int jj = 0; jj < 4; jj++) {
                float s = S[i][jj] * 0.0625f;                    // 1/sqrt(256)
                if (diag && (tx + 16 * jj) > row) s = -1e30f;
                S[i][jj] = s;
                mx = fmaxf(mx, s);
            }
            #pragma unroll
            for (int w = 8; w >= 1; w >>= 1)
                mx = fmaxf(mx, __shfl_xor_sync(0xffffffffu, mx, w));
            float mnew  = fmaxf(m[i], mx);
            float alpha = __expf(m[i] - mnew);
            float ls = 0.f;
            #pragma unroll
            for (int jj = 0; jj < 4; jj++) {
                float p = __expf(S[i][jj] - mnew);
                Ps[row * PSS + tx + 16 * jj] = p;
                ls += p;
            }
            #pragma unroll
            for (int w = 8; w >= 1; w >>= 1)
                ls += __shfl_xor_sync(0xffffffffu, ls, w);
            l[i] = l[i] * alpha + ls;
            m[i] = mnew;
            #pragma unroll
            for (int dc = 0; dc < 4; dc++) {
                O[i][dc].x *= alpha; O[i][dc].y *= alpha;
                O[i][dc].z *= alpha; O[i][dc].w *= alpha;
            }
        }
        __syncwarp();      // P rows are produced & consumed by the same half-warp

        // ---- O += P @ V (V fully resident; thread cols = dc*64 + tx4) ----
        #pragma unroll
        for (int dc = 0; dc < 4; dc++) {
            #pragma unroll 4
            for (int s = 0; s < 64; s += 4) {
                float4 pv[4], vv[4];
                #pragma unroll
                for (int i = 0; i < 4; i++)  pv[i] = *(const float4*)&Ps[(ty4 + i) * PSS + s];
                #pragma unroll
                for (int ss = 0; ss < 4; ss++)
                    vv[ss] = *(const float4*)&Vs[(s + ss) * SMS + dc * 64 + tx4];
                #pragma unroll
                for (int i = 0; i < 4; i++) {
                    O[i][dc].x = fmaf(pv[i].x, vv[0].x, O[i][dc].x);
                    O[i][dc].x = fmaf(pv[i].y, vv[1].x, O[i][dc].x);
                    O[i][dc].x = fmaf(pv[i].z, vv[2].x, O[i][dc].x);
                    O[i][dc].x = fmaf(pv[i].w, vv[3].x, O[i][dc].x);
                    O[i][dc].y = fmaf(pv[i].x, vv[0].y, O[i][dc].y);
                    O[i][dc].y = fmaf(pv[i].y, vv[1].y, O[i][dc].y);
                    O[i][dc].y = fmaf(pv[i].z, vv[2].y, O[i][dc].y);
                    O[i][dc].y = fmaf(pv[i].w, vv[3].y, O[i][dc].y);
                    O[i][dc].z = fmaf(pv[i].x, vv[0].z, O[i][dc].z);
                    O[i][dc].z = fmaf(pv[i].y, vv[1].z, O[i][dc].z);
                    O[i][dc].z = fmaf(pv[i].z, vv[2].z, O[i][dc].z);
                    O[i][dc].z = fmaf(pv[i].w, vv[3].z, O[i][dc].z);
                    O[i][dc].w = fmaf(pv[i].x, vv[0].w, O[i][dc].w);
                    O[i][dc].w = fmaf(pv[i].y, vv[1].w, O[i][dc].w);
                    O[i][dc].w = fmaf(pv[i].z, vv[2].w, O[i][dc].w);
                    O[i][dc].w = fmaf(pv[i].w, vv[3].w, O[i][dc].w);
                }
            }
        }
    }

    // ---- normalize + store ----
    float* obase = g_attnout + ((size_t)b * T_TOK + qb * 64) * DMODEL;
    #pragma unroll
    for (int i = 0; i < 4; i++) {
        float inv = 1.0f / l[i];
        #pragma unroll
        for (int dc = 0; dc < 4; dc++) {
            float4 o = O[i][dc];
            o.x *= inv; o.y *= inv; o.z *= inv; o.w *= inv;
            *(float4*)(obase + (size_t)(ty4 + i) * DMODEL + dc * 64 + tx4) = o;
        }
    }
}

// ---------------------------------------------------------------------------
// K5: pred = attnout @ Wph + bph, fused next-patch MSE accumulation.
// ---------------------------------------------------------------------------
__global__ __launch_bounds__(256) void pred_loss_kernel()
{
    __shared__ float Ws[DMODEL * PATCH];
    int tid = threadIdx.x;
    for (int i = tid; i < DMODEL * PATCH; i += 256) Ws[i] = g_Wph[i];
    __syncthreads();

    int lane = tid & 31, warp = tid >> 5;
    int gw = blockIdx.x * 8 + warp;
    int nw = gridDim.x * 8;
    float bias = g_bph[lane];

    float lsum = 0.f;
    for (int row = gw; row < ROWS; row += nw) {
        const float* orow = g_attnout + (size_t)row * DMODEL;
        float acc = bias;
        #pragma unroll
        for (int kb = 0; kb < 8; kb++) {
            float ov = orow[kb * 32 + lane];
            #pragma unroll
            for (int k2 = 0; k2 < 32; k2++) {
                float o = __shfl_sync(0xffffffffu, ov, k2);
                acc = fmaf(o, Ws[(kb * 32 + k2) * 32 + lane], acc);
            }
        }
        if ((row & (T_TOK - 1)) != T_TOK - 1) {
            float d = acc - g_patches[(size_t)(row + 1) * PATCH + lane];
            lsum = fmaf(d, d, lsum);
        }
    }
    #pragma unroll
    for (int w = 16; w >= 1; w >>= 1)
        lsum += __shfl_xor_sync(0xffffffffu, lsum, w);
    if (lane == 0) atomicAdd(&g_loss_acc, (double)lsum);
}

// ---------------------------------------------------------------------------
// K6: finalize
// ---------------------------------------------------------------------------
__global__ void finalize_kernel(float* out)
{
    out[0] = (float)(g_loss_acc / (double)(BATCH * (T_TOK - 1) * PATCH));
}

// ---------------------------------------------------------------------------
// Launch
// ---------------------------------------------------------------------------
extern "C" void kernel_launch(void* const* d_in, const int* in_sizes, int n_in,
                              void* d_out, int out_size)
{
    const float* x      = (const float*)d_in[0];
    const float* Wproj  = (const float*)d_in[1];
    const float* bproj  = (const float*)d_in[2];
    const float* Wqkv   = (const float*)d_in[3];
    const float* bqkv   = (const float*)d_in[4];
    const float* Wout   = (const float*)d_in[5];
    const float* bout   = (const float*)d_in[6];
    const float* Whead  = (const float*)d_in[7];
    const float* bhead  = (const float*)d_in[8];
    float* out = (float*)d_out;

    cudaFuncSetAttribute(attention_kernel,
                         cudaFuncAttributeMaxDynamicSharedMemorySize, ATTN_SMEM);

    prep_kernel<<<132, 256>>>(Wproj, bproj, Wqkv, bqkv, Wout, bout, Whead, bhead);
    instnorm_kernel<<<BATCH, 256>>>(x);
    qkv_gemm_kernel<<<dim3(QKV_N / 64, ROWS / 64), 256>>>();
    attention_kernel<<<512, 256, ATTN_SMEM>>>();
    pred_loss_kernel<<<256, 256>>>();
    finalize_kernel<<<1, 1>>>(out);
}